// round 1
// baseline (speedup 1.0000x reference)
#include <cuda_runtime.h>
#include <math.h>

#define BB 8192
#define TT 96
#define FF 64
#define HH 256
#define K3 768
#define TB 16
#define TBP 18          // padded row stride (floats): 8B-aligned, low bank conflict
#define NPAIR (TB/2)

// Persistent recurrence state (device globals: allocation-free)
__device__ float g_h[BB * HH];
__device__ float g_prev[BB];

// ---- packed f32x2 helpers (sm_100+) ----
__device__ __forceinline__ unsigned long long pack2dup(float v) {
    unsigned long long r;
    asm("mov.b64 %0, {%1, %1};" : "=l"(r) : "f"(v));
    return r;
}
__device__ __forceinline__ void unpack2(unsigned long long v, float& lo, float& hi) {
    asm("mov.b64 {%0, %1}, %2;" : "=f"(lo), "=f"(hi) : "l"(v));
}
__device__ __forceinline__ void fma2(unsigned long long& d, unsigned long long a,
                                     unsigned long long b) {
    asm("fma.rn.f32x2 %0, %1, %2, %0;" : "+l"(d) : "l"(a), "l"(b));
}

__device__ __forceinline__ float sigmoidf_(float x) {
    return 1.0f / (1.0f + __expf(-x));
}

__global__ void init_kernel(const float* __restrict__ init_state,
                            const float* __restrict__ init_inp) {
    int i = blockIdx.x * blockDim.x + threadIdx.x;
    if (i < BB * HH) g_h[i] = init_state[i];
    if (i < BB) g_prev[i] = init_inp[i];
}

__global__ __launch_bounds__(256, 2) void step_kernel(
    const float* __restrict__ feat,   // [B,T,F]
    const float* __restrict__ Kw,     // [65, 768]
    const float* __restrict__ Rw,     // [256, 768]
    const float* __restrict__ ib,     // [768]
    const float* __restrict__ rb,     // [768]
    const float* __restrict__ dw,     // [256]
    const float* __restrict__ db,     // [1]
    float* __restrict__ out,          // [B,T]
    int t) {
    __shared__ __align__(16) float s_x[FF + 1][TBP];
    __shared__ __align__(16) float s_h[HH][TBP];

    const int j = threadIdx.x;        // hidden column 0..255
    const int b0 = blockIdx.x * TB;   // batch tile start

    // Load h tile transposed: s_h[k][b] = h[b0+b][k]. Global coalesced over j.
#pragma unroll
    for (int b = 0; b < TB; b++)
        s_h[j][b] = g_h[(size_t)(b0 + b) * HH + j];

    if (j < TB) s_x[0][j] = g_prev[b0 + j];
    for (int idx = j; idx < TB * FF; idx += 256) {
        int b = idx / FF, f = idx % FF;
        s_x[1 + f][b] = feat[((size_t)(b0 + b) * TT + t) * FF + f];
    }
    __syncthreads();

    unsigned long long az[NPAIR], ar[NPAIR], ahx[NPAIR], ahh[NPAIR];
#pragma unroll
    for (int p = 0; p < NPAIR; p++) { az[p] = ar[p] = ahx[p] = ahh[p] = 0ULL; }

    // ---------- x phase: k = 0..64 over [prev_out, feat] ----------
    {
        const float* wp = Kw + j;
        float nwz = wp[0], nwr = wp[HH], nwh = wp[2 * HH];
#pragma unroll 1
        for (int k = 0; k < FF + 1; k++) {
            float cwz = nwz, cwr = nwr, cwh = nwh;
            if (k + 1 < FF + 1) {             // prefetch next weight row
                const float* np = Kw + (k + 1) * K3 + j;
                nwz = np[0]; nwr = np[HH]; nwh = np[2 * HH];
            }
            unsigned long long wz = pack2dup(cwz);
            unsigned long long wr = pack2dup(cwr);
            unsigned long long wh = pack2dup(cwh);
#pragma unroll
            for (int p = 0; p < NPAIR; p++) {
                unsigned long long xv =
                    *reinterpret_cast<const unsigned long long*>(&s_x[k][2 * p]);
                fma2(az[p], xv, wz);
                fma2(ar[p], xv, wr);
                fma2(ahx[p], xv, wh);
            }
        }
    }

    // ---------- h phase: k = 0..255 over hidden state ----------
    {
        const float* wp = Rw + j;
        float nwz = wp[0], nwr = wp[HH], nwh = wp[2 * HH];
#pragma unroll 1
        for (int k = 0; k < HH; k++) {
            float cwz = nwz, cwr = nwr, cwh = nwh;
            if (k + 1 < HH) {
                const float* np = Rw + (k + 1) * K3 + j;
                nwz = np[0]; nwr = np[HH]; nwh = np[2 * HH];
            }
            unsigned long long wz = pack2dup(cwz);
            unsigned long long wr = pack2dup(cwr);
            unsigned long long wh = pack2dup(cwh);
#pragma unroll
            for (int p = 0; p < NPAIR; p++) {
                unsigned long long hv =
                    *reinterpret_cast<const unsigned long long*>(&s_h[k][2 * p]);
                fma2(az[p], hv, wz);
                fma2(ar[p], hv, wr);
                fma2(ahh[p], hv, wh);
            }
        }
    }

    const float biz = ib[j] + rb[j];
    const float bir = ib[HH + j] + rb[HH + j];
    const float bhx = ib[2 * HH + j];
    const float bhh = rb[2 * HH + j];
    const float dwj = dw[j];

    float hnew[TB];
#pragma unroll
    for (int p = 0; p < NPAIR; p++) {
        float z0, z1, r0, r1, cx0, cx1, ch0, ch1;
        unpack2(az[p], z0, z1);
        unpack2(ar[p], r0, r1);
        unpack2(ahx[p], cx0, cx1);
        unpack2(ahh[p], ch0, ch1);
        float hold0 = s_h[j][2 * p];
        float hold1 = s_h[j][2 * p + 1];
        float zz0 = sigmoidf_(z0 + biz), zz1 = sigmoidf_(z1 + biz);
        float rr0 = sigmoidf_(r0 + bir), rr1 = sigmoidf_(r1 + bir);
        float c0 = tanhf(cx0 + bhx + rr0 * (ch0 + bhh));
        float c1 = tanhf(cx1 + bhx + rr1 * (ch1 + bhh));
        hnew[2 * p] = zz0 * hold0 + (1.0f - zz0) * c0;
        hnew[2 * p + 1] = zz1 * hold1 + (1.0f - zz1) * c1;
    }

    __syncthreads();  // all reads of s_h done; safe to overwrite
#pragma unroll
    for (int b = 0; b < TB; b++) {
        g_h[(size_t)(b0 + b) * HH + j] = hnew[b];
        s_h[j][b] = hnew[b] * dwj;  // premultiply for dense reduction
    }
    __syncthreads();

    // out[b] = sum_j hnew[b][j]*dw[j] + db ; warp w reduces rows 2w, 2w+1
    const int w = j >> 5, lane = j & 31;
#pragma unroll
    for (int rr = 0; rr < 2; rr++) {
        int b = 2 * w + rr;
        float s = 0.0f;
#pragma unroll
        for (int m = 0; m < HH / 32; m++) s += s_h[lane + 32 * m][b];
#pragma unroll
        for (int off = 16; off; off >>= 1)
            s += __shfl_down_sync(0xffffffffu, s, off);
        if (lane == 0) {
            float v = s + db[0];
            out[(size_t)(b0 + b) * TT + t] = v;
            g_prev[b0 + b] = v;
        }
    }
}

extern "C" void kernel_launch(void* const* d_in, const int* in_sizes, int n_in,
                              void* d_out, int out_size) {
    const float* feat  = (const float*)d_in[0];  // decoder_feature [B,T,F]
    const float* hs0   = (const float*)d_in[1];  // init_state [B,H]
    const float* inp0  = (const float*)d_in[2];  // decoder_init_input [B,1]
    const float* Kw    = (const float*)d_in[3];  // kernel [65,768]
    const float* Rw    = (const float*)d_in[4];  // recurrent_kernel [256,768]
    const float* ibias = (const float*)d_in[5];  // input_bias [768]
    const float* rbias = (const float*)d_in[6];  // recurrent_bias [768]
    const float* dw    = (const float*)d_in[7];  // dense_w [256,1]
    const float* db    = (const float*)d_in[8];  // dense_b [1]
    float* out = (float*)d_out;                  // [B,T,1]

    init_kernel<<<(BB * HH + 255) / 256, 256>>>(hs0, inp0);
    for (int t = 0; t < TT; t++)
        step_kernel<<<BB / TB, 256>>>(feat, Kw, Rw, ibias, rbias, dw, db, out, t);
}